// round 1
// baseline (speedup 1.0000x reference)
#include <cuda_runtime.h>

// out[i,j,k] = C[i,j,k] * x[i,j]
// B=4096, INPUT_SIZE=512, EMBED_DIM=64
// Pure HBM-streaming kernel: float4 vectorized, one x scalar per 4-element group.

__global__ void bcast_mul_kernel(const float* __restrict__ x,
                                 const float4* __restrict__ C4,
                                 float4* __restrict__ out4,
                                 long long n4) {
    long long i = (long long)blockIdx.x * blockDim.x + threadIdx.x;
    if (i >= n4) return;
    // 64 floats per (i,j) row -> 16 float4 groups per x scalar
    float s = __ldg(&x[i >> 4]);
    float4 c = C4[i];
    float4 o;
    o.x = c.x * s;
    o.y = c.y * s;
    o.z = c.z * s;
    o.w = c.w * s;
    out4[i] = o;
}

extern "C" void kernel_launch(void* const* d_in, const int* in_sizes, int n_in,
                              void* d_out, int out_size) {
    // Identify inputs by size: x is the small one (B*INPUT_SIZE), C the big one.
    const float* x = nullptr;
    const float* C = nullptr;
    if (in_sizes[0] < in_sizes[1]) {
        x = (const float*)d_in[0];
        C = (const float*)d_in[1];
    } else {
        x = (const float*)d_in[1];
        C = (const float*)d_in[0];
    }

    long long n = (long long)out_size;      // 4096*512*64 = 134217728
    long long n4 = n >> 2;                  // float4 groups

    const int threads = 256;
    long long blocks = (n4 + threads - 1) / threads;

    bcast_mul_kernel<<<(unsigned)blocks, threads>>>(
        x, (const float4*)C, (float4*)d_out, n4);
}

// round 2
// speedup vs baseline: 1.0259x; 1.0259x over previous
#include <cuda_runtime.h>

// out[i,j,k] = C[i,j,k] * x[i,j]
// B=4096, INPUT_SIZE=512, EMBED_DIM=64  -> n = 134,217,728 floats, n4 = 33,554,432 float4
//
// HBM-streaming kernel, v2:
//  - 4x unrolled grid-stride: each thread owns 4 float4s at stride gridDim*blockDim
//    (each j-slice stays perfectly coalesced; MLP_p1 ~ 8 front-batched loads)
//  - __ldcs on C, __stcs on out (read/write-once streams, evict-first) so the
//    64x-reused x stays L2 resident.

#define UNROLL 4

__global__ void bcast_mul_kernel(const float* __restrict__ x,
                                 const float4* __restrict__ C4,
                                 float4* __restrict__ out4,
                                 long long n4) {
    const long long stride = (long long)gridDim.x * blockDim.x;
    const long long base = (long long)blockIdx.x * blockDim.x + threadIdx.x;

    long long idx[UNROLL];
    float4 c[UNROLL];
    float  s[UNROLL];
    bool   ok[UNROLL];

    // Front-batch all loads -> high MLP, single long_scoreboard drain.
#pragma unroll
    for (int j = 0; j < UNROLL; j++) {
        idx[j] = base + (long long)j * stride;
        ok[j] = idx[j] < n4;
        if (ok[j]) {
            c[j] = __ldcs(&C4[idx[j]]);
            s[j] = __ldg(&x[idx[j] >> 4]);   // 16 float4-groups per x scalar
        }
    }

#pragma unroll
    for (int j = 0; j < UNROLL; j++) {
        if (ok[j]) {
            float4 o;
            o.x = c[j].x * s[j];
            o.y = c[j].y * s[j];
            o.z = c[j].z * s[j];
            o.w = c[j].w * s[j];
            __stcs(&out4[idx[j]], o);
        }
    }
}

extern "C" void kernel_launch(void* const* d_in, const int* in_sizes, int n_in,
                              void* d_out, int out_size) {
    // Identify inputs by size: x is the small one (B*INPUT_SIZE), C the big one.
    const float* x;
    const float* C;
    if (in_sizes[0] < in_sizes[1]) {
        x = (const float*)d_in[0];
        C = (const float*)d_in[1];
    } else {
        x = (const float*)d_in[1];
        C = (const float*)d_in[0];
    }

    long long n  = (long long)out_size;   // 134217728
    long long n4 = n >> 2;                // 33554432 float4 groups

    const int threads = 256;
    long long blocks = (n4 + (long long)threads * UNROLL - 1) / ((long long)threads * UNROLL);

    bcast_mul_kernel<<<(unsigned)blocks, threads>>>(
        x, (const float4*)C, (float4*)d_out, n4);
}

// round 3
// speedup vs baseline: 1.0321x; 1.0061x over previous
#include <cuda_runtime.h>

// out[i,j,k] = C[i,j,k] * x[i,j]
// B=4096, INPUT_SIZE=512, EMBED_DIM=64 -> n = 2^27 floats, n4 = 2^25 float4
//
// v3: 32-bit indexing, 8x unroll, block-contiguous tiles (block owns 2048
// consecutive float4s; thread j-slices at +256). Uniform-branch tail only.

#define THREADS 256
#define UNROLL  8

__global__ void bcast_mul_kernel(const float* __restrict__ x,
                                 const float4* __restrict__ C4,
                                 float4* __restrict__ out4,
                                 unsigned n4) {
    const unsigned base = blockIdx.x * (THREADS * UNROLL) + threadIdx.x;

    if (base + (UNROLL - 1) * THREADS < n4) {
        // Fast path (all blocks when n4 divides exactly): no predication.
        float4 c[UNROLL];
        float  s[UNROLL];
#pragma unroll
        for (int j = 0; j < UNROLL; j++) {
            unsigned i = base + j * THREADS;
            c[j] = __ldcs(&C4[i]);
            s[j] = __ldg(&x[i >> 4]);      // 16 float4-groups per x scalar
        }
#pragma unroll
        for (int j = 0; j < UNROLL; j++) {
            unsigned i = base + j * THREADS;
            float4 o;
            o.x = c[j].x * s[j];
            o.y = c[j].y * s[j];
            o.z = c[j].z * s[j];
            o.w = c[j].w * s[j];
            __stcs(&out4[i], o);
        }
    } else {
        // Tail path (never taken for the bench shape).
#pragma unroll
        for (int j = 0; j < UNROLL; j++) {
            unsigned i = base + j * THREADS;
            if (i < n4) {
                float s = __ldg(&x[i >> 4]);
                float4 c = __ldcs(&C4[i]);
                float4 o;
                o.x = c.x * s; o.y = c.y * s; o.z = c.z * s; o.w = c.w * s;
                __stcs(&out4[i], o);
            }
        }
    }
}

extern "C" void kernel_launch(void* const* d_in, const int* in_sizes, int n_in,
                              void* d_out, int out_size) {
    const float* x;
    const float* C;
    if (in_sizes[0] < in_sizes[1]) {
        x = (const float*)d_in[0];
        C = (const float*)d_in[1];
    } else {
        x = (const float*)d_in[1];
        C = (const float*)d_in[0];
    }

    unsigned n4 = (unsigned)((long long)out_size >> 2);   // 33,554,432
    unsigned per_block = THREADS * UNROLL;                 // 2048
    unsigned blocks = (n4 + per_block - 1) / per_block;    // 16384

    bcast_mul_kernel<<<blocks, THREADS>>>(
        x, (const float4*)C, (float4*)d_out, n4);
}

// round 4
// speedup vs baseline: 1.0365x; 1.0043x over previous
#include <cuda_runtime.h>

// out[i,j,k] = C[i,j,k] * x[i,j]
// B=4096, INPUT_SIZE=512, EMBED_DIM=64 -> n = 2^27 floats, n4 = 2^25 float4
//
// v4: 512 threads x 8 unroll, block-contiguous 4096-float4 tiles (64KB r + 64KB w
// per block), no predication in the exact-division fast kernel. Generic fallback
// kernel only if shape ever changes.

#define THREADS 512
#define UNROLL  8

__global__ __launch_bounds__(THREADS)
void bcast_mul_exact(const float* __restrict__ x,
                     const float4* __restrict__ C4,
                     float4* __restrict__ out4) {
    const unsigned base = blockIdx.x * (THREADS * UNROLL) + threadIdx.x;

    float4 c[UNROLL];
    float  s[UNROLL];
#pragma unroll
    for (int j = 0; j < UNROLL; j++) {
        unsigned i = base + j * THREADS;
        c[j] = __ldcs(&C4[i]);
        s[j] = __ldg(&x[i >> 4]);          // 16 float4-groups per x scalar
    }
#pragma unroll
    for (int j = 0; j < UNROLL; j++) {
        unsigned i = base + j * THREADS;
        float4 o;
        o.x = c[j].x * s[j];
        o.y = c[j].y * s[j];
        o.z = c[j].z * s[j];
        o.w = c[j].w * s[j];
        __stcs(&out4[i], o);
    }
}

__global__ void bcast_mul_generic(const float* __restrict__ x,
                                  const float4* __restrict__ C4,
                                  float4* __restrict__ out4,
                                  unsigned n4) {
    unsigned i = blockIdx.x * blockDim.x + threadIdx.x;
    if (i < n4) {
        float s = __ldg(&x[i >> 4]);
        float4 c = __ldcs(&C4[i]);
        float4 o;
        o.x = c.x * s; o.y = c.y * s; o.z = c.z * s; o.w = c.w * s;
        __stcs(&out4[i], o);
    }
}

extern "C" void kernel_launch(void* const* d_in, const int* in_sizes, int n_in,
                              void* d_out, int out_size) {
    const float* x;
    const float* C;
    if (in_sizes[0] < in_sizes[1]) {
        x = (const float*)d_in[0];
        C = (const float*)d_in[1];
    } else {
        x = (const float*)d_in[1];
        C = (const float*)d_in[0];
    }

    unsigned n4 = (unsigned)((long long)out_size >> 2);   // 33,554,432
    const unsigned per_block = THREADS * UNROLL;          // 4096

    if (n4 % per_block == 0) {
        bcast_mul_exact<<<n4 / per_block, THREADS>>>(
            x, (const float4*)C, (float4*)d_out);
    } else {
        bcast_mul_generic<<<(n4 + 255) / 256, 256>>>(
            x, (const float4*)C, (float4*)d_out, n4);
    }
}